// round 1
// baseline (speedup 1.0000x reference)
#include <cuda_runtime.h>
#include <cstdint>
#include <cstddef>

#define BB 4
#define NN 16384
#define NPT 1024
#define NS 32
#define CF 64
#define CIN 67

// scratch: neighbor indices (B, NPOINT, NSAMPLE)
__device__ int g_nidx[BB * NPT * NS];

// ---------------------------------------------------------------------------
// FPS: one CTA per batch. xyz SoA in dynamic smem; dists register-resident.
// Exact replication of reference arithmetic: ((dx*dx + dy*dy) + dz*dz), rn,
// no fma contraction. Tie-break = smallest original index (atomicMin pass).
// ---------------------------------------------------------------------------
__global__ __launch_bounds__(1024, 1) void fps_kernel(const float* __restrict__ xyz,
                                                      float* __restrict__ newxyz) {
    extern __shared__ float sm[];
    float* sx = sm;
    float* sy = sm + NN;
    float* sz = sm + 2 * NN;
    __shared__ float s_wmax[32];
    __shared__ float s_best;
    __shared__ int s_bestidx;

    const int b = blockIdx.x;
    const int tid = threadIdx.x;
    const float* base = xyz + (size_t)b * NN * 3;

    for (int i = tid; i < NN; i += 1024) {
        sx[i] = base[3 * i + 0];
        sy[i] = base[3 * i + 1];
        sz[i] = base[3 * i + 2];
    }

    float dist[16];
#pragma unroll
    for (int k = 0; k < 16; k++) dist[k] = 1e10f;

    __syncthreads();

    int f = 0;
    float* outp = newxyz + (size_t)b * NPT * 3;

    for (int p = 0; p < NPT; ++p) {
        const float cx = sx[f], cy = sy[f], cz = sz[f];
        if (tid == 0) {
            outp[3 * p + 0] = cx;
            outp[3 * p + 1] = cy;
            outp[3 * p + 2] = cz;
        }
        float best = -1.0f;
#pragma unroll
        for (int k = 0; k < 16; k++) {
            const int i = tid + k * 1024;
            const float dx = __fadd_rn(sx[i], -cx);
            const float dy = __fadd_rn(sy[i], -cy);
            const float dz = __fadd_rn(sz[i], -cz);
            const float d2 =
                __fadd_rn(__fadd_rn(__fmul_rn(dx, dx), __fmul_rn(dy, dy)), __fmul_rn(dz, dz));
            const float nd = fminf(dist[k], d2);
            dist[k] = nd;
            best = fmaxf(best, nd);
        }
        // block max (value only)
#pragma unroll
        for (int off = 16; off; off >>= 1)
            best = fmaxf(best, __shfl_xor_sync(0xffffffffu, best, off));
        if ((tid & 31) == 0) s_wmax[tid >> 5] = best;
        __syncthreads();
        if (tid < 32) {
            float v = s_wmax[tid];
#pragma unroll
            for (int off = 16; off; off >>= 1)
                v = fmaxf(v, __shfl_xor_sync(0xffffffffu, v, off));
            if (tid == 0) {
                s_best = v;
                s_bestidx = 0x7fffffff;
            }
        }
        __syncthreads();
        // index pass: first (smallest-index) point achieving the max
        const float gb = s_best;
#pragma unroll
        for (int k = 0; k < 16; k++) {
            if (dist[k] == gb) atomicMin(&s_bestidx, tid + k * 1024);
        }
        __syncthreads();
        f = s_bestidx;
    }
}

// ---------------------------------------------------------------------------
// Ball query: one warp per centroid. Scan points in index order, append the
// first 32 within radius (strict d2 < 0.01f), pad with the first hit.
// ---------------------------------------------------------------------------
__global__ __launch_bounds__(256) void ball_kernel(const float* __restrict__ xyz,
                                                   const float* __restrict__ newxyz) {
    const int gw = (int)((blockIdx.x * blockDim.x + threadIdx.x) >> 5);
    const int lane = threadIdx.x & 31;
    if (gw >= BB * NPT) return;
    const int b = gw >> 10;

    const float* nx = newxyz + (size_t)gw * 3;
    const float cx = nx[0], cy = nx[1], cz = nx[2];
    const float* px = xyz + (size_t)b * NN * 3;
    int* out = g_nidx + (size_t)gw * NS;

    int count = 0;
    int first = 0;
    bool havefirst = false;

    for (int bs = 0; bs < NN; bs += 32) {
        const int i = bs + lane;
        const float dx = __fadd_rn(px[3 * i + 0], -cx);
        const float dy = __fadd_rn(px[3 * i + 1], -cy);
        const float dz = __fadd_rn(px[3 * i + 2], -cz);
        const float d2 =
            __fadd_rn(__fadd_rn(__fmul_rn(dx, dx), __fmul_rn(dy, dy)), __fmul_rn(dz, dz));
        const bool win = d2 < 0.01f;
        const unsigned m = __ballot_sync(0xffffffffu, win);
        if (m) {
            if (!havefirst) {
                first = bs + __ffs(m) - 1;
                havefirst = true;
            }
            const int slot = count + __popc(m & ((1u << lane) - 1u));
            if (win && slot < NS) out[slot] = i;
            count += __popc(m);
            if (count >= NS) break;
        }
    }
    if (lane >= count) out[lane] = first;  // pad (count<32 case); no-op if count>=32
}

// ---------------------------------------------------------------------------
// Gather + 3-layer MLP + max-pool. One warp per centroid, lane = sample.
// Weights in smem (LDS.128 broadcast, 1 LDS : 4 FMA). 8-wide accumulator ILP.
// h1/h2 live in per-thread local (coalesced, L1-resident), float4 accesses.
// ---------------------------------------------------------------------------
__global__ __launch_bounds__(128) void mlp_kernel(
    const float* __restrict__ xyz, const float* __restrict__ feat,
    const float* __restrict__ w1, const float* __restrict__ b1,
    const float* __restrict__ w2, const float* __restrict__ b2,
    const float* __restrict__ w3, const float* __restrict__ b3,
    const float* __restrict__ newxyz, float* __restrict__ outf) {
    extern __shared__ float sm[];
    float* sw1 = sm;                 // 64 x 68 (padded)
    float* sw2 = sw1 + 64 * 68;      // 64 x 64
    float* sw3 = sw2 + 64 * 64;      // 128 x 64
    float* sb1 = sw3 + 128 * 64;     // 64
    float* sb2 = sb1 + 64;           // 64
    float* sb3 = sb2 + 64;           // 128

    const int tid = threadIdx.x;
    for (int i = tid; i < 64 * CIN; i += 128) sw1[(i / CIN) * 68 + (i % CIN)] = w1[i];
    for (int i = tid; i < 64 * 64; i += 128) sw2[i] = w2[i];
    for (int i = tid; i < 128 * 64; i += 128) sw3[i] = w3[i];
    if (tid < 64) {
        sb1[tid] = b1[tid];
        sb2[tid] = b2[tid];
    }
    if (tid < 128) sb3[tid] = b3[tid];
    __syncthreads();

    const int warp = tid >> 5, lane = tid & 31;
    const int pc = blockIdx.x * 4 + warp;  // global centroid id
    const int b = pc >> 10, p = pc & 1023;

    const int idx = g_nidx[pc * NS + lane];
    const float* P = xyz + ((size_t)b * NN + idx) * 3;
    const float* NXp = newxyz + (size_t)pc * 3;

    float in[CIN];
    in[0] = P[0] - NXp[0];
    in[1] = P[1] - NXp[1];
    in[2] = P[2] - NXp[2];
    const float4* F = (const float4*)(feat + ((size_t)b * NN + idx) * CF);
#pragma unroll
    for (int q = 0; q < 16; q++) {
        const float4 v = F[q];
        in[3 + 4 * q] = v.x;
        in[4 + 4 * q] = v.y;
        in[5 + 4 * q] = v.z;
        in[6 + 4 * q] = v.w;
    }

    float h1[64] __attribute__((aligned(16)));
#pragma unroll 1
    for (int o = 0; o < 64; o += 8) {
        float acc[8];
#pragma unroll
        for (int j = 0; j < 8; j++) acc[j] = sb1[o + j];
#pragma unroll
        for (int c = 0; c < 64; c += 4) {
#pragma unroll
            for (int j = 0; j < 8; j++) {
                const float4 w = *(const float4*)&sw1[(o + j) * 68 + c];
                acc[j] = fmaf(in[c + 0], w.x, acc[j]);
                acc[j] = fmaf(in[c + 1], w.y, acc[j]);
                acc[j] = fmaf(in[c + 2], w.z, acc[j]);
                acc[j] = fmaf(in[c + 3], w.w, acc[j]);
            }
        }
#pragma unroll
        for (int j = 0; j < 8; j++) {
            acc[j] = fmaf(in[64], sw1[(o + j) * 68 + 64], acc[j]);
            acc[j] = fmaf(in[65], sw1[(o + j) * 68 + 65], acc[j]);
            acc[j] = fmaf(in[66], sw1[(o + j) * 68 + 66], acc[j]);
            h1[o + j] = fmaxf(acc[j], 0.0f);
        }
    }

    float h2[64] __attribute__((aligned(16)));
#pragma unroll 1
    for (int o = 0; o < 64; o += 8) {
        float acc[8];
#pragma unroll
        for (int j = 0; j < 8; j++) acc[j] = sb2[o + j];
#pragma unroll
        for (int c = 0; c < 64; c += 4) {
            const float4 hv = *(const float4*)&h1[c];
#pragma unroll
            for (int j = 0; j < 8; j++) {
                const float4 w = *(const float4*)&sw2[(o + j) * 64 + c];
                acc[j] = fmaf(hv.x, w.x, acc[j]);
                acc[j] = fmaf(hv.y, w.y, acc[j]);
                acc[j] = fmaf(hv.z, w.z, acc[j]);
                acc[j] = fmaf(hv.w, w.w, acc[j]);
            }
        }
#pragma unroll
        for (int j = 0; j < 8; j++) h2[o + j] = fmaxf(acc[j], 0.0f);
    }

    const size_t obase = ((size_t)b * 128) * NPT + p;
#pragma unroll 1
    for (int o = 0; o < 128; o += 8) {
        float acc[8];
#pragma unroll
        for (int j = 0; j < 8; j++) acc[j] = sb3[o + j];
#pragma unroll
        for (int c = 0; c < 64; c += 4) {
            const float4 hv = *(const float4*)&h2[c];
#pragma unroll
            for (int j = 0; j < 8; j++) {
                const float4 w = *(const float4*)&sw3[(o + j) * 64 + c];
                acc[j] = fmaf(hv.x, w.x, acc[j]);
                acc[j] = fmaf(hv.y, w.y, acc[j]);
                acc[j] = fmaf(hv.z, w.z, acc[j]);
                acc[j] = fmaf(hv.w, w.w, acc[j]);
            }
        }
#pragma unroll
        for (int j = 0; j < 8; j++) {
            float v = fmaxf(acc[j], 0.0f);  // relu then max over samples
#pragma unroll
            for (int off = 16; off; off >>= 1)
                v = fmaxf(v, __shfl_xor_sync(0xffffffffu, v, off));
            if (lane == 0) outf[obase + (size_t)(o + j) * NPT] = v;
        }
    }
}

// ---------------------------------------------------------------------------
extern "C" void kernel_launch(void* const* d_in, const int* in_sizes, int n_in,
                              void* d_out, int out_size) {
    const float* xyz = (const float*)d_in[0];
    const float* feat = (const float*)d_in[1];
    const float* w1 = (const float*)d_in[2];
    const float* b1 = (const float*)d_in[3];
    const float* w2 = (const float*)d_in[4];
    const float* b2 = (const float*)d_in[5];
    const float* w3 = (const float*)d_in[6];
    const float* b3 = (const float*)d_in[7];

    float* out = (float*)d_out;
    float* newxyz = out;                  // (B, NPOINT, 3)
    float* outf = out + BB * NPT * 3;     // (B, 128, NPOINT)

    const int fps_smem = 3 * NN * 4;      // 196608 B
    const int mlp_smem = (64 * 68 + 64 * 64 + 128 * 64 + 64 + 64 + 128) * 4;  // 67584 B

    cudaFuncSetAttribute(fps_kernel, cudaFuncAttributeMaxDynamicSharedMemorySize, fps_smem);
    cudaFuncSetAttribute(mlp_kernel, cudaFuncAttributeMaxDynamicSharedMemorySize, mlp_smem);

    fps_kernel<<<BB, 1024, fps_smem>>>(xyz, newxyz);
    ball_kernel<<<(BB * NPT * 32) / 256, 256>>>(xyz, newxyz);
    mlp_kernel<<<BB * NPT / 4, 128, mlp_smem>>>(xyz, feat, w1, b1, w2, b2, w3, b3, newxyz, outf);
}

// round 2
// speedup vs baseline: 1.7128x; 1.7128x over previous
#include <cuda_runtime.h>
#include <cstdint>
#include <cstddef>

#define BB 4
#define NN 16384
#define NPT 1024
#define NS 32
#define CF 64
#define CIN 67

// scratch: neighbor indices (B, NPOINT, NSAMPLE)
__device__ int g_nidx[BB * NPT * NS];

// ---- packed f32x2 helpers (per-lane IEEE rn, identical to scalar __fadd_rn/__fmul_rn)
typedef unsigned long long u64;
__device__ __forceinline__ u64 f2_add(u64 a, u64 b) {
    u64 r;
    asm("add.rn.f32x2 %0, %1, %2;" : "=l"(r) : "l"(a), "l"(b));
    return r;
}
__device__ __forceinline__ u64 f2_mul(u64 a, u64 b) {
    u64 r;
    asm("mul.rn.f32x2 %0, %1, %2;" : "=l"(r) : "l"(a), "l"(b));
    return r;
}
__device__ __forceinline__ u64 f2_pack(float lo, float hi) {
    u64 r;
    asm("mov.b64 %0, {%1, %2};" : "=l"(r) : "f"(lo), "f"(hi));
    return r;
}
__device__ __forceinline__ float2 f2_unpack(u64 v) {
    float2 r;
    asm("mov.b64 {%0, %1}, %2;" : "=f"(r.x), "=f"(r.y) : "l"(v));
    return r;
}

// ---------------------------------------------------------------------------
// FPS: one CTA per batch. Points paired (i, i+1024) and packed into smem:
//   A[q*1024+t] = ulonglong2{ (x_a,x_b), (y_a,y_b) }   (LDS.128)
//   Z[q*1024+t] = (z_a,z_b)                            (LDS.64)
// where a = t + 2q*1024, b = t + (2q+1)*1024.
// Distance update in packed f32x2 (exact same rounding as scalar rn ops).
// Tie-break = smallest original index via equality pass + atomicMin.
// ---------------------------------------------------------------------------
__global__ __launch_bounds__(1024, 1) void fps_kernel(const float* __restrict__ xyz,
                                                      float* __restrict__ newxyz) {
    extern __shared__ unsigned char smraw[];
    ulonglong2* A = (ulonglong2*)smraw;            // 8*1024 entries, 128 KB
    u64* Z = (u64*)(smraw + 8 * 1024 * 16);        // 8*1024 entries, 64 KB
    __shared__ float s_wmax[32];
    __shared__ int s_bidx[2];

    const int b = blockIdx.x;
    const int tid = threadIdx.x;
    const float* base = xyz + (size_t)b * NN * 3;

#pragma unroll
    for (int q = 0; q < 8; q++) {
        const int ia = tid + (2 * q) * 1024;
        const int ib = ia + 1024;
        ulonglong2 av;
        av.x = f2_pack(base[3 * ia + 0], base[3 * ib + 0]);
        av.y = f2_pack(base[3 * ia + 1], base[3 * ib + 1]);
        A[q * 1024 + tid] = av;
        Z[q * 1024 + tid] = f2_pack(base[3 * ia + 2], base[3 * ib + 2]);
    }
    if (tid == 0) {
        s_bidx[0] = 0x7fffffff;
        s_bidx[1] = 0x7fffffff;
    }

    float2 dist2[8];
#pragma unroll
    for (int q = 0; q < 8; q++) dist2[q] = make_float2(1e10f, 1e10f);

    __syncthreads();

    int f = 0;
    float* outp = newxyz + (size_t)b * NPT * 3;

    for (int p = 0; p < NPT; ++p) {
        // fetch centroid coords (broadcast LDS from packed layout)
        const int ft = f & 1023;
        const int fk = f >> 10;
        const int fq = fk >> 1;
        const int fh = fk & 1;
        const ulonglong2 fa = A[fq * 1024 + ft];
        const float2 fxy0 = f2_unpack(fa.x);
        const float2 fxy1 = f2_unpack(fa.y);
        const float2 fz = f2_unpack(Z[fq * 1024 + ft]);
        const float cx = fh ? fxy0.y : fxy0.x;
        const float cy = fh ? fxy1.y : fxy1.x;
        const float cz = fh ? fz.y : fz.x;
        if (tid == 0) {
            outp[3 * p + 0] = cx;
            outp[3 * p + 1] = cy;
            outp[3 * p + 2] = cz;
        }
        const u64 ncx = f2_pack(-cx, -cx);
        const u64 ncy = f2_pack(-cy, -cy);
        const u64 ncz = f2_pack(-cz, -cz);

        float b0 = -1.0f, b1 = -1.0f;
#pragma unroll
        for (int q = 0; q < 8; q++) {
            const ulonglong2 av = A[q * 1024 + tid];
            const u64 zv = Z[q * 1024 + tid];
            const u64 dx = f2_add(av.x, ncx);
            const u64 dy = f2_add(av.y, ncy);
            const u64 dz = f2_add(zv, ncz);
            const u64 d2p =
                f2_add(f2_add(f2_mul(dx, dx), f2_mul(dy, dy)), f2_mul(dz, dz));
            const float2 d = f2_unpack(d2p);
            const float n0 = fminf(dist2[q].x, d.x);
            const float n1 = fminf(dist2[q].y, d.y);
            dist2[q].x = n0;
            dist2[q].y = n1;
            b0 = fmaxf(b0, n0);
            b1 = fmaxf(b1, n1);
        }
        float best = fmaxf(b0, b1);
#pragma unroll
        for (int off = 16; off; off >>= 1)
            best = fmaxf(best, __shfl_xor_sync(0xffffffffu, best, off));
        if ((tid & 31) == 0) s_wmax[tid >> 5] = best;
        __syncthreads();
        // every warp redundantly reduces the 32 warp maxima (no broadcast barrier)
        float v = s_wmax[tid & 31];
#pragma unroll
        for (int off = 16; off; off >>= 1)
            v = fmaxf(v, __shfl_xor_sync(0xffffffffu, v, off));
        // equality pass: smallest original index achieving the block max
        int* bslot = &s_bidx[p & 1];
#pragma unroll
        for (int q = 0; q < 8; q++) {
            if (dist2[q].x == v) atomicMin(bslot, tid + (2 * q) * 1024);
            if (dist2[q].y == v) atomicMin(bslot, tid + (2 * q + 1) * 1024);
        }
        __syncthreads();
        f = *bslot;
        if (tid == 0) s_bidx[(p + 1) & 1] = 0x7fffffff;  // other slot: no race
    }
}

// ---------------------------------------------------------------------------
// Ball query: one warp per centroid. Scan points in index order, append the
// first 32 within radius (strict d2 < 0.01f), pad with the first hit.
// ---------------------------------------------------------------------------
__global__ __launch_bounds__(256) void ball_kernel(const float* __restrict__ xyz,
                                                   const float* __restrict__ newxyz) {
    const int gw = (int)((blockIdx.x * blockDim.x + threadIdx.x) >> 5);
    const int lane = threadIdx.x & 31;
    if (gw >= BB * NPT) return;
    const int b = gw >> 10;

    const float* nx = newxyz + (size_t)gw * 3;
    const float cx = nx[0], cy = nx[1], cz = nx[2];
    const float* px = xyz + (size_t)b * NN * 3;
    int* out = g_nidx + (size_t)gw * NS;

    int count = 0;
    int first = 0;
    bool havefirst = false;

    for (int bs = 0; bs < NN; bs += 32) {
        const int i = bs + lane;
        const float dx = __fadd_rn(px[3 * i + 0], -cx);
        const float dy = __fadd_rn(px[3 * i + 1], -cy);
        const float dz = __fadd_rn(px[3 * i + 2], -cz);
        const float d2 =
            __fadd_rn(__fadd_rn(__fmul_rn(dx, dx), __fmul_rn(dy, dy)), __fmul_rn(dz, dz));
        const bool win = d2 < 0.01f;
        const unsigned m = __ballot_sync(0xffffffffu, win);
        if (m) {
            if (!havefirst) {
                first = bs + __ffs(m) - 1;
                havefirst = true;
            }
            const int slot = count + __popc(m & ((1u << lane) - 1u));
            if (win && slot < NS) out[slot] = i;
            count += __popc(m);
            if (count >= NS) break;
        }
    }
    if (lane >= count) out[lane] = first;  // pad (count<32 case); no-op if count>=32
}

// ---------------------------------------------------------------------------
// Gather + 3-layer MLP + max-pool. One warp per centroid, lane = sample.
// Weights in smem (LDS.128 broadcast, 1 LDS : 4 FMA). 8-wide accumulator ILP.
// ---------------------------------------------------------------------------
__global__ __launch_bounds__(128) void mlp_kernel(
    const float* __restrict__ xyz, const float* __restrict__ feat,
    const float* __restrict__ w1, const float* __restrict__ b1,
    const float* __restrict__ w2, const float* __restrict__ b2,
    const float* __restrict__ w3, const float* __restrict__ b3,
    const float* __restrict__ newxyz, float* __restrict__ outf) {
    extern __shared__ float sm[];
    float* sw1 = sm;                 // 64 x 68 (padded)
    float* sw2 = sw1 + 64 * 68;      // 64 x 64
    float* sw3 = sw2 + 64 * 64;      // 128 x 64
    float* sb1 = sw3 + 128 * 64;     // 64
    float* sb2 = sb1 + 64;           // 64
    float* sb3 = sb2 + 64;           // 128

    const int tid = threadIdx.x;
    for (int i = tid; i < 64 * CIN; i += 128) sw1[(i / CIN) * 68 + (i % CIN)] = w1[i];
    for (int i = tid; i < 64 * 64; i += 128) sw2[i] = w2[i];
    for (int i = tid; i < 128 * 64; i += 128) sw3[i] = w3[i];
    if (tid < 64) {
        sb1[tid] = b1[tid];
        sb2[tid] = b2[tid];
    }
    if (tid < 128) sb3[tid] = b3[tid];
    __syncthreads();

    const int warp = tid >> 5, lane = tid & 31;
    const int pc = blockIdx.x * 4 + warp;  // global centroid id
    const int b = pc >> 10, p = pc & 1023;

    const int idx = g_nidx[pc * NS + lane];
    const float* P = xyz + ((size_t)b * NN + idx) * 3;
    const float* NXp = newxyz + (size_t)pc * 3;

    float in[CIN];
    in[0] = P[0] - NXp[0];
    in[1] = P[1] - NXp[1];
    in[2] = P[2] - NXp[2];
    const float4* F = (const float4*)(feat + ((size_t)b * NN + idx) * CF);
#pragma unroll
    for (int q = 0; q < 16; q++) {
        const float4 v = F[q];
        in[3 + 4 * q] = v.x;
        in[4 + 4 * q] = v.y;
        in[5 + 4 * q] = v.z;
        in[6 + 4 * q] = v.w;
    }

    float h1[64] __attribute__((aligned(16)));
#pragma unroll 1
    for (int o = 0; o < 64; o += 8) {
        float acc[8];
#pragma unroll
        for (int j = 0; j < 8; j++) acc[j] = sb1[o + j];
#pragma unroll
        for (int c = 0; c < 64; c += 4) {
#pragma unroll
            for (int j = 0; j < 8; j++) {
                const float4 w = *(const float4*)&sw1[(o + j) * 68 + c];
                acc[j] = fmaf(in[c + 0], w.x, acc[j]);
                acc[j] = fmaf(in[c + 1], w.y, acc[j]);
                acc[j] = fmaf(in[c + 2], w.z, acc[j]);
                acc[j] = fmaf(in[c + 3], w.w, acc[j]);
            }
        }
#pragma unroll
        for (int j = 0; j < 8; j++) {
            acc[j] = fmaf(in[64], sw1[(o + j) * 68 + 64], acc[j]);
            acc[j] = fmaf(in[65], sw1[(o + j) * 68 + 65], acc[j]);
            acc[j] = fmaf(in[66], sw1[(o + j) * 68 + 66], acc[j]);
            h1[o + j] = fmaxf(acc[j], 0.0f);
        }
    }

    float h2[64] __attribute__((aligned(16)));
#pragma unroll 1
    for (int o = 0; o < 64; o += 8) {
        float acc[8];
#pragma unroll
        for (int j = 0; j < 8; j++) acc[j] = sb2[o + j];
#pragma unroll
        for (int c = 0; c < 64; c += 4) {
            const float4 hv = *(const float4*)&h1[c];
#pragma unroll
            for (int j = 0; j < 8; j++) {
                const float4 w = *(const float4*)&sw2[(o + j) * 64 + c];
                acc[j] = fmaf(hv.x, w.x, acc[j]);
                acc[j] = fmaf(hv.y, w.y, acc[j]);
                acc[j] = fmaf(hv.z, w.z, acc[j]);
                acc[j] = fmaf(hv.w, w.w, acc[j]);
            }
        }
#pragma unroll
        for (int j = 0; j < 8; j++) h2[o + j] = fmaxf(acc[j], 0.0f);
    }

    const size_t obase = ((size_t)b * 128) * NPT + p;
#pragma unroll 1
    for (int o = 0; o < 128; o += 8) {
        float acc[8];
#pragma unroll
        for (int j = 0; j < 8; j++) acc[j] = sb3[o + j];
#pragma unroll
        for (int c = 0; c < 64; c += 4) {
            const float4 hv = *(const float4*)&h2[c];
#pragma unroll
            for (int j = 0; j < 8; j++) {
                const float4 w = *(const float4*)&sw3[(o + j) * 64 + c];
                acc[j] = fmaf(hv.x, w.x, acc[j]);
                acc[j] = fmaf(hv.y, w.y, acc[j]);
                acc[j] = fmaf(hv.z, w.z, acc[j]);
                acc[j] = fmaf(hv.w, w.w, acc[j]);
            }
        }
#pragma unroll
        for (int j = 0; j < 8; j++) {
            float v = fmaxf(acc[j], 0.0f);  // relu then max over samples
#pragma unroll
            for (int off = 16; off; off >>= 1)
                v = fmaxf(v, __shfl_xor_sync(0xffffffffu, v, off));
            if (lane == 0) outf[obase + (size_t)(o + j) * NPT] = v;
        }
    }
}

// ---------------------------------------------------------------------------
extern "C" void kernel_launch(void* const* d_in, const int* in_sizes, int n_in,
                              void* d_out, int out_size) {
    const float* xyz = (const float*)d_in[0];
    const float* feat = (const float*)d_in[1];
    const float* w1 = (const float*)d_in[2];
    const float* b1 = (const float*)d_in[3];
    const float* w2 = (const float*)d_in[4];
    const float* b2 = (const float*)d_in[5];
    const float* w3 = (const float*)d_in[6];
    const float* b3 = (const float*)d_in[7];

    float* out = (float*)d_out;
    float* newxyz = out;                  // (B, NPOINT, 3)
    float* outf = out + BB * NPT * 3;     // (B, 128, NPOINT)

    const int fps_smem = 8 * 1024 * 16 + 8 * 1024 * 8;  // 196608 B
    const int mlp_smem = (64 * 68 + 64 * 64 + 128 * 64 + 64 + 64 + 128) * 4;  // 67584 B

    cudaFuncSetAttribute(fps_kernel, cudaFuncAttributeMaxDynamicSharedMemorySize, fps_smem);
    cudaFuncSetAttribute(mlp_kernel, cudaFuncAttributeMaxDynamicSharedMemorySize, mlp_smem);

    fps_kernel<<<BB, 1024, fps_smem>>>(xyz, newxyz);
    ball_kernel<<<(BB * NPT * 32) / 256, 256>>>(xyz, newxyz);
    mlp_kernel<<<BB * NPT / 4, 128, mlp_smem>>>(xyz, feat, w1, b1, w2, b2, w3, b3, newxyz, outf);
}

// round 3
// speedup vs baseline: 2.1850x; 1.2756x over previous
#include <cuda_runtime.h>
#include <cstdint>
#include <cstddef>

#define BB 4
#define NN 16384
#define NPT 1024
#define NS 32
#define CF 64
#define CIN 67
#define CL 4  // CTAs per cluster (one cluster per batch)

// scratch: neighbor indices (B, NPOINT, NSAMPLE)
__device__ int g_nidx[BB * NPT * NS];

// ---- packed f32x2 helpers (per-lane IEEE rn, identical to scalar __fadd_rn/__fmul_rn)
typedef unsigned long long u64;
__device__ __forceinline__ u64 f2_add(u64 a, u64 b) {
    u64 r;
    asm("add.rn.f32x2 %0, %1, %2;" : "=l"(r) : "l"(a), "l"(b));
    return r;
}
__device__ __forceinline__ u64 f2_mul(u64 a, u64 b) {
    u64 r;
    asm("mul.rn.f32x2 %0, %1, %2;" : "=l"(r) : "l"(a), "l"(b));
    return r;
}
__device__ __forceinline__ u64 f2_pack(float lo, float hi) {
    u64 r;
    asm("mov.b64 %0, {%1, %2};" : "=l"(r) : "f"(lo), "f"(hi));
    return r;
}
__device__ __forceinline__ float2 f2_unpack(u64 v) {
    float2 r;
    asm("mov.b64 {%0, %1}, %2;" : "=f"(r.x), "=f"(r.y) : "l"(v));
    return r;
}
// key = (float_bits(dist) << 32) | negidx  (dist >= 0 -> u64 order == (dist, -idx) order)
__device__ __forceinline__ u64 mkkey(float v, uint32_t negidx) {
    u64 r;
    asm("mov.b64 %0, {%1, %2};" : "=l"(r) : "r"(negidx), "r"(__float_as_uint(v)));
    return r;
}
__device__ __forceinline__ u64 umax64(u64 a, u64 b) { return a > b ? a : b; }

__device__ __forceinline__ uint32_t smem_u32(const void* p) {
    return (uint32_t)__cvta_generic_to_shared(p);
}
__device__ __forceinline__ void st_cluster_u64(uint32_t laddr, uint32_t rank, u64 v) {
    uint32_t r;
    asm volatile("mapa.shared::cluster.u32 %0, %1, %2;" : "=r"(r) : "r"(laddr), "r"(rank));
    asm volatile("st.shared::cluster.u64 [%0], %1;" ::"r"(r), "l"(v) : "memory");
}
__device__ __forceinline__ void cluster_sync_all() {
    asm volatile("barrier.cluster.arrive.aligned;" ::: "memory");
    asm volatile("barrier.cluster.wait.aligned;" ::: "memory");
}

// ---------------------------------------------------------------------------
// FPS: 4-CTA cluster per batch. Every CTA holds a FULL packed xyz copy in smem
// (slot s packs points (s, s+8192)), but updates dists only for its 4096
// points (slots rank*2048 .. rank*2048+2047). Argmax carried as a u64 key
// (dist bits << 32 | ~idx) -> exact first-max (smallest index) semantics.
// Cross-CTA: partial keys exchanged via parity-double-buffered DSMEM
// mailboxes + one cluster.sync per iteration.
// ---------------------------------------------------------------------------
__global__ __launch_bounds__(1024, 1) __cluster_dims__(CL, 1, 1)
void fps_kernel(const float* __restrict__ xyz, float* __restrict__ newxyz) {
    extern __shared__ unsigned char smraw[];
    ulonglong2* A = (ulonglong2*)smraw;            // 8192 x 16B = 128 KB
    u64* Z = (u64*)(smraw + 8192 * 16);            // 8192 x 8B  =  64 KB
    __shared__ u64 s_part[32];
    __shared__ u64 mbox[2][CL];

    const int b = blockIdx.x / CL;
    const int rank = blockIdx.x % CL;
    const int tid = threadIdx.x;
    const float* base = xyz + (size_t)b * NN * 3;

    // full packed copy (every CTA)
    for (int s = tid; s < 8192; s += 1024) {
        const int ia = s, ib = s + 8192;
        ulonglong2 av;
        av.x = f2_pack(base[3 * ia + 0], base[3 * ib + 0]);
        av.y = f2_pack(base[3 * ia + 1], base[3 * ib + 1]);
        A[s] = av;
        Z[s] = f2_pack(base[3 * ia + 2], base[3 * ib + 2]);
    }

    const int s0 = rank * 2048 + tid;  // this thread's two slots
    const int s1 = s0 + 1024;
    const uint32_t ni0a = ~(uint32_t)s0;
    const uint32_t ni0b = ~(uint32_t)(s0 + 8192);
    const uint32_t ni1a = ~(uint32_t)s1;
    const uint32_t ni1b = ~(uint32_t)(s1 + 8192);

    float2 d20 = make_float2(1e10f, 1e10f);
    float2 d21 = make_float2(1e10f, 1e10f);

    __syncthreads();
    cluster_sync_all();  // remote smem safe from here

    int f = 0;
    float* outp = newxyz + (size_t)b * NPT * 3;
    const int lane = tid & 31, wid = tid >> 5;

    for (int p = 0; p < NPT; ++p) {
        // centroid fetch (local, full copy)
        const int fslot = f & 8191;
        const int fhalf = f >> 13;
        const ulonglong2 fa = A[fslot];
        const float2 fx = f2_unpack(fa.x);
        const float2 fy = f2_unpack(fa.y);
        const float2 fz = f2_unpack(Z[fslot]);
        const float cx = fhalf ? fx.y : fx.x;
        const float cy = fhalf ? fy.y : fy.x;
        const float cz = fhalf ? fz.y : fz.x;
        if (rank == 0 && tid == 0) {
            outp[3 * p + 0] = cx;
            outp[3 * p + 1] = cy;
            outp[3 * p + 2] = cz;
        }
        const u64 ncx = f2_pack(-cx, -cx);
        const u64 ncy = f2_pack(-cy, -cy);
        const u64 ncz = f2_pack(-cz, -cz);

        u64 loc;
        {
            const ulonglong2 av = A[s0];
            const u64 zv = Z[s0];
            const u64 dx = f2_add(av.x, ncx);
            const u64 dy = f2_add(av.y, ncy);
            const u64 dz = f2_add(zv, ncz);
            const float2 d =
                f2_unpack(f2_add(f2_add(f2_mul(dx, dx), f2_mul(dy, dy)), f2_mul(dz, dz)));
            d20.x = fminf(d20.x, d.x);
            d20.y = fminf(d20.y, d.y);
            loc = umax64(mkkey(d20.x, ni0a), mkkey(d20.y, ni0b));
        }
        {
            const ulonglong2 av = A[s1];
            const u64 zv = Z[s1];
            const u64 dx = f2_add(av.x, ncx);
            const u64 dy = f2_add(av.y, ncy);
            const u64 dz = f2_add(zv, ncz);
            const float2 d =
                f2_unpack(f2_add(f2_add(f2_mul(dx, dx), f2_mul(dy, dy)), f2_mul(dz, dz)));
            d21.x = fminf(d21.x, d.x);
            d21.y = fminf(d21.y, d.y);
            loc = umax64(loc, umax64(mkkey(d21.x, ni1a), mkkey(d21.y, ni1b)));
        }

        // intra-warp u64 max reduce
#pragma unroll
        for (int off = 16; off; off >>= 1)
            loc = umax64(loc, __shfl_xor_sync(0xffffffffu, loc, off));
        if (lane == 0) s_part[wid] = loc;
        __syncthreads();
        // all warps redundantly reduce the 32 warp partials
        u64 v = s_part[lane];
#pragma unroll
        for (int off = 16; off; off >>= 1)
            v = umax64(v, __shfl_xor_sync(0xffffffffu, v, off));

        // broadcast CTA partial to all cluster CTAs (parity double buffer)
        const int par = p & 1;
        if (tid < CL) st_cluster_u64(smem_u32(&mbox[par][rank]), tid, v);
        cluster_sync_all();

        const u64 g = umax64(umax64(mbox[par][0], mbox[par][1]),
                             umax64(mbox[par][2], mbox[par][3]));
        f = (int)(~(uint32_t)g);
    }
}

// ---------------------------------------------------------------------------
// Ball query: one warp per centroid. Scan points in index order, append the
// first 32 within radius (strict d2 < 0.01f), pad with the first hit.
// ---------------------------------------------------------------------------
__global__ __launch_bounds__(256) void ball_kernel(const float* __restrict__ xyz,
                                                   const float* __restrict__ newxyz) {
    const int gw = (int)((blockIdx.x * blockDim.x + threadIdx.x) >> 5);
    const int lane = threadIdx.x & 31;
    if (gw >= BB * NPT) return;
    const int b = gw >> 10;

    const float* nx = newxyz + (size_t)gw * 3;
    const float cx = nx[0], cy = nx[1], cz = nx[2];
    const float* px = xyz + (size_t)b * NN * 3;
    int* out = g_nidx + (size_t)gw * NS;

    int count = 0;
    int first = 0;
    bool havefirst = false;

    for (int bs = 0; bs < NN; bs += 32) {
        const int i = bs + lane;
        const float dx = __fadd_rn(px[3 * i + 0], -cx);
        const float dy = __fadd_rn(px[3 * i + 1], -cy);
        const float dz = __fadd_rn(px[3 * i + 2], -cz);
        const float d2 =
            __fadd_rn(__fadd_rn(__fmul_rn(dx, dx), __fmul_rn(dy, dy)), __fmul_rn(dz, dz));
        const bool win = d2 < 0.01f;
        const unsigned m = __ballot_sync(0xffffffffu, win);
        if (m) {
            if (!havefirst) {
                first = bs + __ffs(m) - 1;
                havefirst = true;
            }
            const int slot = count + __popc(m & ((1u << lane) - 1u));
            if (win && slot < NS) out[slot] = i;
            count += __popc(m);
            if (count >= NS) break;
        }
    }
    if (lane >= count) out[lane] = first;  // pad (count<32 case); no-op if count>=32
}

// ---------------------------------------------------------------------------
// Gather + 3-layer MLP + max-pool. One warp per centroid, lane = sample.
// Weights in smem (LDS.128 broadcast, 1 LDS : 4 FMA). 8-wide accumulator ILP.
// ---------------------------------------------------------------------------
__global__ __launch_bounds__(128) void mlp_kernel(
    const float* __restrict__ xyz, const float* __restrict__ feat,
    const float* __restrict__ w1, const float* __restrict__ b1,
    const float* __restrict__ w2, const float* __restrict__ b2,
    const float* __restrict__ w3, const float* __restrict__ b3,
    const float* __restrict__ newxyz, float* __restrict__ outf) {
    extern __shared__ float sm[];
    float* sw1 = sm;                 // 64 x 68 (padded)
    float* sw2 = sw1 + 64 * 68;      // 64 x 64
    float* sw3 = sw2 + 64 * 64;      // 128 x 64
    float* sb1 = sw3 + 128 * 64;     // 64
    float* sb2 = sb1 + 64;           // 64
    float* sb3 = sb2 + 64;           // 128

    const int tid = threadIdx.x;
    for (int i = tid; i < 64 * CIN; i += 128) sw1[(i / CIN) * 68 + (i % CIN)] = w1[i];
    for (int i = tid; i < 64 * 64; i += 128) sw2[i] = w2[i];
    for (int i = tid; i < 128 * 64; i += 128) sw3[i] = w3[i];
    if (tid < 64) {
        sb1[tid] = b1[tid];
        sb2[tid] = b2[tid];
    }
    if (tid < 128) sb3[tid] = b3[tid];
    __syncthreads();

    const int warp = tid >> 5, lane = tid & 31;
    const int pc = blockIdx.x * 4 + warp;  // global centroid id
    const int b = pc >> 10, p = pc & 1023;

    const int idx = g_nidx[pc * NS + lane];
    const float* P = xyz + ((size_t)b * NN + idx) * 3;
    const float* NXp = newxyz + (size_t)pc * 3;

    float in[CIN];
    in[0] = P[0] - NXp[0];
    in[1] = P[1] - NXp[1];
    in[2] = P[2] - NXp[2];
    const float4* F = (const float4*)(feat + ((size_t)b * NN + idx) * CF);
#pragma unroll
    for (int q = 0; q < 16; q++) {
        const float4 v = F[q];
        in[3 + 4 * q] = v.x;
        in[4 + 4 * q] = v.y;
        in[5 + 4 * q] = v.z;
        in[6 + 4 * q] = v.w;
    }

    float h1[64] __attribute__((aligned(16)));
#pragma unroll 1
    for (int o = 0; o < 64; o += 8) {
        float acc[8];
#pragma unroll
        for (int j = 0; j < 8; j++) acc[j] = sb1[o + j];
#pragma unroll
        for (int c = 0; c < 64; c += 4) {
#pragma unroll
            for (int j = 0; j < 8; j++) {
                const float4 w = *(const float4*)&sw1[(o + j) * 68 + c];
                acc[j] = fmaf(in[c + 0], w.x, acc[j]);
                acc[j] = fmaf(in[c + 1], w.y, acc[j]);
                acc[j] = fmaf(in[c + 2], w.z, acc[j]);
                acc[j] = fmaf(in[c + 3], w.w, acc[j]);
            }
        }
#pragma unroll
        for (int j = 0; j < 8; j++) {
            acc[j] = fmaf(in[64], sw1[(o + j) * 68 + 64], acc[j]);
            acc[j] = fmaf(in[65], sw1[(o + j) * 68 + 65], acc[j]);
            acc[j] = fmaf(in[66], sw1[(o + j) * 68 + 66], acc[j]);
            h1[o + j] = fmaxf(acc[j], 0.0f);
        }
    }

    float h2[64] __attribute__((aligned(16)));
#pragma unroll 1
    for (int o = 0; o < 64; o += 8) {
        float acc[8];
#pragma unroll
        for (int j = 0; j < 8; j++) acc[j] = sb2[o + j];
#pragma unroll
        for (int c = 0; c < 64; c += 4) {
            const float4 hv = *(const float4*)&h1[c];
#pragma unroll
            for (int j = 0; j < 8; j++) {
                const float4 w = *(const float4*)&sw2[(o + j) * 64 + c];
                acc[j] = fmaf(hv.x, w.x, acc[j]);
                acc[j] = fmaf(hv.y, w.y, acc[j]);
                acc[j] = fmaf(hv.z, w.z, acc[j]);
                acc[j] = fmaf(hv.w, w.w, acc[j]);
            }
        }
#pragma unroll
        for (int j = 0; j < 8; j++) h2[o + j] = fmaxf(acc[j], 0.0f);
    }

    const size_t obase = ((size_t)b * 128) * NPT + p;
#pragma unroll 1
    for (int o = 0; o < 128; o += 8) {
        float acc[8];
#pragma unroll
        for (int j = 0; j < 8; j++) acc[j] = sb3[o + j];
#pragma unroll
        for (int c = 0; c < 64; c += 4) {
            const float4 hv = *(const float4*)&h2[c];
#pragma unroll
            for (int j = 0; j < 8; j++) {
                const float4 w = *(const float4*)&sw3[(o + j) * 64 + c];
                acc[j] = fmaf(hv.x, w.x, acc[j]);
                acc[j] = fmaf(hv.y, w.y, acc[j]);
                acc[j] = fmaf(hv.z, w.z, acc[j]);
                acc[j] = fmaf(hv.w, w.w, acc[j]);
            }
        }
#pragma unroll
        for (int j = 0; j < 8; j++) {
            float v = fmaxf(acc[j], 0.0f);  // relu then max over samples
#pragma unroll
            for (int off = 16; off; off >>= 1)
                v = fmaxf(v, __shfl_xor_sync(0xffffffffu, v, off));
            if (lane == 0) outf[obase + (size_t)(o + j) * NPT] = v;
        }
    }
}

// ---------------------------------------------------------------------------
extern "C" void kernel_launch(void* const* d_in, const int* in_sizes, int n_in,
                              void* d_out, int out_size) {
    const float* xyz = (const float*)d_in[0];
    const float* feat = (const float*)d_in[1];
    const float* w1 = (const float*)d_in[2];
    const float* b1 = (const float*)d_in[3];
    const float* w2 = (const float*)d_in[4];
    const float* b2 = (const float*)d_in[5];
    const float* w3 = (const float*)d_in[6];
    const float* b3 = (const float*)d_in[7];

    float* out = (float*)d_out;
    float* newxyz = out;                  // (B, NPOINT, 3)
    float* outf = out + BB * NPT * 3;     // (B, 128, NPOINT)

    const int fps_smem = 8192 * 16 + 8192 * 8;  // 196608 B (full packed copy)
    const int mlp_smem = (64 * 68 + 64 * 64 + 128 * 64 + 64 + 64 + 128) * 4;  // 67584 B

    cudaFuncSetAttribute(fps_kernel, cudaFuncAttributeMaxDynamicSharedMemorySize, fps_smem);
    cudaFuncSetAttribute(mlp_kernel, cudaFuncAttributeMaxDynamicSharedMemorySize, mlp_smem);

    fps_kernel<<<BB * CL, 1024, fps_smem>>>(xyz, newxyz);
    ball_kernel<<<(BB * NPT * 32) / 256, 256>>>(xyz, newxyz);
    mlp_kernel<<<BB * NPT / 4, 128, mlp_smem>>>(xyz, feat, w1, b1, w2, b2, w3, b3, newxyz, outf);
}

// round 4
// speedup vs baseline: 2.7730x; 1.2691x over previous
#include <cuda_runtime.h>
#include <cstdint>
#include <cstddef>

#define BB 4
#define NN 16384
#define NPT 1024
#define NS 32
#define CF 64
#define CIN 67
#define CL 4  // CTAs per cluster (one cluster per batch)

// scratch: neighbor indices (B, NPOINT, NSAMPLE)
__device__ int g_nidx[BB * NPT * NS];

// ---- packed f32x2 helpers (per-lane IEEE rn, identical to scalar __fadd_rn/__fmul_rn)
typedef unsigned long long u64;
__device__ __forceinline__ u64 f2_add(u64 a, u64 b) {
    u64 r;
    asm("add.rn.f32x2 %0, %1, %2;" : "=l"(r) : "l"(a), "l"(b));
    return r;
}
__device__ __forceinline__ u64 f2_mul(u64 a, u64 b) {
    u64 r;
    asm("mul.rn.f32x2 %0, %1, %2;" : "=l"(r) : "l"(a), "l"(b));
    return r;
}
__device__ __forceinline__ u64 f2_pack(float lo, float hi) {
    u64 r;
    asm("mov.b64 %0, {%1, %2};" : "=l"(r) : "f"(lo), "f"(hi));
    return r;
}
__device__ __forceinline__ float2 f2_unpack(u64 v) {
    float2 r;
    asm("mov.b64 {%0, %1}, %2;" : "=f"(r.x), "=f"(r.y) : "l"(v));
    return r;
}
__device__ __forceinline__ u64 umax64(u64 a, u64 b) { return a > b ? a : b; }
__device__ __forceinline__ uint32_t redux_max(uint32_t v) {
    uint32_t r;
    asm("redux.sync.max.u32 %0, %1, 0xffffffff;" : "=r"(r) : "r"(v));
    return r;
}
__device__ __forceinline__ uint32_t smem_u32(const void* p) {
    return (uint32_t)__cvta_generic_to_shared(p);
}
__device__ __forceinline__ void st_cluster_u64(uint32_t laddr, uint32_t rank, u64 v) {
    uint32_t r;
    asm volatile("mapa.shared::cluster.u32 %0, %1, %2;" : "=r"(r) : "r"(laddr), "r"(rank));
    asm volatile("st.relaxed.cluster.shared::cluster.u64 [%0], %1;" ::"r"(r), "l"(v)
                 : "memory");
}
__device__ __forceinline__ u64 ld_mbox(uint32_t laddr) {
    u64 v;
    asm volatile("ld.relaxed.cluster.shared::cta.u64 %0, [%1];" : "=l"(v) : "r"(laddr)
                 : "memory");
    return v;
}
__device__ __forceinline__ void cluster_sync_all() {
    asm volatile("barrier.cluster.arrive.aligned;" ::: "memory");
    asm volatile("barrier.cluster.wait.aligned;" ::: "memory");
}

// payload: dist_bits(32) << 21 | negidx(14)    (bits 14..20 zero)
// mailbox: (p+1)(11) << 53 | payload
// With equal tags, u64 max == (dist, -idx) lexicographic max == jnp.argmax semantics.

// ---------------------------------------------------------------------------
// FPS: 4-CTA cluster per batch. Every CTA holds a FULL packed xyz copy in smem
// (slot s packs points (s, s+8192)); each CTA updates dists for its 4096
// points only. Per-iteration sync = tagged DSMEM mailboxes (no cluster.sync).
// ---------------------------------------------------------------------------
__global__ __launch_bounds__(1024, 1) __cluster_dims__(CL, 1, 1)
void fps_kernel(const float* __restrict__ xyz, float* __restrict__ newxyz) {
    extern __shared__ unsigned char smraw[];
    ulonglong2* A = (ulonglong2*)smraw;            // 8192 x 16B = 128 KB
    u64* Z = (u64*)(smraw + 8192 * 16);            // 8192 x 8B  =  64 KB
    __shared__ u64 s_part[32];
    __shared__ u64 mbox[2][CL];

    const int b = blockIdx.x / CL;
    const int rank = blockIdx.x % CL;
    const int tid = threadIdx.x;
    const float* base = xyz + (size_t)b * NN * 3;

    // full packed copy (every CTA)
    for (int s = tid; s < 8192; s += 1024) {
        const int ia = s, ib = s + 8192;
        ulonglong2 av;
        av.x = f2_pack(base[3 * ia + 0], base[3 * ib + 0]);
        av.y = f2_pack(base[3 * ia + 1], base[3 * ib + 1]);
        A[s] = av;
        Z[s] = f2_pack(base[3 * ia + 2], base[3 * ib + 2]);
    }
    if (tid < 2 * CL) ((u64*)mbox)[tid] = 0;  // tags start at 1; 0 never matches

    const int s0 = rank * 2048 + tid;  // this thread's two slots
    const int s1 = s0 + 1024;
    const uint32_t ni0a = (uint32_t)(16383 - s0);
    const uint32_t ni0b = (uint32_t)(16383 - (s0 + 8192));
    const uint32_t ni1a = (uint32_t)(16383 - s1);
    const uint32_t ni1b = (uint32_t)(16383 - (s1 + 8192));

    float2 d20 = make_float2(1e10f, 1e10f);
    float2 d21 = make_float2(1e10f, 1e10f);

    __syncthreads();
    cluster_sync_all();  // mailboxes initialized cluster-wide from here

    int f = 0;
    float* outp = newxyz + (size_t)b * NPT * 3;
    const int lane = tid & 31, wid = tid >> 5;
    const uint32_t mb0 = smem_u32(&mbox[0][0]);

    for (int p = 0; p < NPT; ++p) {
        // centroid fetch (local, full copy)
        const int fslot = f & 8191;
        const int fhalf = f >> 13;
        const ulonglong2 fa = A[fslot];
        const float2 fx = f2_unpack(fa.x);
        const float2 fy = f2_unpack(fa.y);
        const float2 fz = f2_unpack(Z[fslot]);
        const float cx = fhalf ? fx.y : fx.x;
        const float cy = fhalf ? fy.y : fy.x;
        const float cz = fhalf ? fz.y : fz.x;
        if (rank == 0 && tid == 0) {
            outp[3 * p + 0] = cx;
            outp[3 * p + 1] = cy;
            outp[3 * p + 2] = cz;
        }
        const u64 ncx = f2_pack(-cx, -cx);
        const u64 ncy = f2_pack(-cy, -cy);
        const u64 ncz = f2_pack(-cz, -cz);

        u64 loc;
        {
            const ulonglong2 av = A[s0];
            const u64 zv = Z[s0];
            const u64 dx = f2_add(av.x, ncx);
            const u64 dy = f2_add(av.y, ncy);
            const u64 dz = f2_add(zv, ncz);
            const float2 d =
                f2_unpack(f2_add(f2_add(f2_mul(dx, dx), f2_mul(dy, dy)), f2_mul(dz, dz)));
            d20.x = fminf(d20.x, d.x);
            d20.y = fminf(d20.y, d.y);
            const u64 k0 = ((u64)__float_as_uint(d20.x) << 21) | ni0a;
            const u64 k1 = ((u64)__float_as_uint(d20.y) << 21) | ni0b;
            loc = umax64(k0, k1);
        }
        {
            const ulonglong2 av = A[s1];
            const u64 zv = Z[s1];
            const u64 dx = f2_add(av.x, ncx);
            const u64 dy = f2_add(av.y, ncy);
            const u64 dz = f2_add(zv, ncz);
            const float2 d =
                f2_unpack(f2_add(f2_add(f2_mul(dx, dx), f2_mul(dy, dy)), f2_mul(dz, dz)));
            d21.x = fminf(d21.x, d.x);
            d21.y = fminf(d21.y, d.y);
            const u64 k0 = ((u64)__float_as_uint(d21.x) << 21) | ni1a;
            const u64 k1 = ((u64)__float_as_uint(d21.y) << 21) | ni1b;
            loc = umax64(loc, umax64(k0, k1));
        }

        // warp argmax via two redux ops
        {
            const uint32_t dbits = (uint32_t)(loc >> 21);
            const uint32_t wmax = redux_max(dbits);
            const uint32_t cand = (dbits == wmax) ? (uint32_t)(loc & 0x3FFFu) : 0u;
            const uint32_t nmax = redux_max(cand);
            if (lane == 0) s_part[wid] = ((u64)wmax << 21) | nmax;
        }
        __syncthreads();

        const int par = p & 1;
        if (wid == 0) {
            // stage 2: reduce 32 CTA partials, publish to all 4 ranks (tagged)
            const u64 v = s_part[lane];
            const uint32_t dbits = (uint32_t)(v >> 21);
            const uint32_t wmax = redux_max(dbits);
            const uint32_t cand = (dbits == wmax) ? (uint32_t)(v & 0x3FFFu) : 0u;
            const uint32_t nmax = redux_max(cand);
            const u64 msg = ((u64)(p + 1) << 53) | ((u64)wmax << 21) | nmax;
            if (lane < CL)
                st_cluster_u64(mb0 + (uint32_t)(par * CL + rank) * 8u, (uint32_t)lane, msg);
        }

        // poll the 4 mailbox entries for this parity
        const u64 want = (u64)(p + 1) << 53;
        u64 g = 0;
#pragma unroll
        for (int j = 0; j < CL; j++) {
            const uint32_t a = mb0 + (uint32_t)(par * CL + j) * 8u;
            u64 v;
            do {
                v = ld_mbox(a);
            } while ((v >> 53) != (u64)(p + 1));
            g = umax64(g, v);
        }
        (void)want;
        f = 16383 - (int)(g & 0x3FFFu);
    }
    cluster_sync_all();  // no CTA exits while peers may still store into it
}

// ---------------------------------------------------------------------------
// Ball query: one warp per centroid. Scan points in index order, append the
// first 32 within radius (strict d2 < 0.01f), pad with the first hit.
// ---------------------------------------------------------------------------
__global__ __launch_bounds__(256) void ball_kernel(const float* __restrict__ xyz,
                                                   const float* __restrict__ newxyz) {
    const int gw = (int)((blockIdx.x * blockDim.x + threadIdx.x) >> 5);
    const int lane = threadIdx.x & 31;
    if (gw >= BB * NPT) return;
    const int b = gw >> 10;

    const float* nx = newxyz + (size_t)gw * 3;
    const float cx = nx[0], cy = nx[1], cz = nx[2];
    const float* px = xyz + (size_t)b * NN * 3;
    int* out = g_nidx + (size_t)gw * NS;

    int count = 0;
    int first = 0;
    bool havefirst = false;

    for (int bs = 0; bs < NN; bs += 32) {
        const int i = bs + lane;
        const float dx = __fadd_rn(px[3 * i + 0], -cx);
        const float dy = __fadd_rn(px[3 * i + 1], -cy);
        const float dz = __fadd_rn(px[3 * i + 2], -cz);
        const float d2 =
            __fadd_rn(__fadd_rn(__fmul_rn(dx, dx), __fmul_rn(dy, dy)), __fmul_rn(dz, dz));
        const bool win = d2 < 0.01f;
        const unsigned m = __ballot_sync(0xffffffffu, win);
        if (m) {
            if (!havefirst) {
                first = bs + __ffs(m) - 1;
                havefirst = true;
            }
            const int slot = count + __popc(m & ((1u << lane) - 1u));
            if (win && slot < NS) out[slot] = i;
            count += __popc(m);
            if (count >= NS) break;
        }
    }
    if (lane >= count) out[lane] = first;  // pad (count<32 case); no-op if count>=32
}

// ---------------------------------------------------------------------------
// Gather + 3-layer MLP + max-pool. One warp per centroid, lane = sample.
// Weights in smem (LDS.128 broadcast, 1 LDS : 4 FMA). 8-wide accumulator ILP.
// ---------------------------------------------------------------------------
__global__ __launch_bounds__(128) void mlp_kernel(
    const float* __restrict__ xyz, const float* __restrict__ feat,
    const float* __restrict__ w1, const float* __restrict__ b1,
    const float* __restrict__ w2, const float* __restrict__ b2,
    const float* __restrict__ w3, const float* __restrict__ b3,
    const float* __restrict__ newxyz, float* __restrict__ outf) {
    extern __shared__ float sm[];
    float* sw1 = sm;                 // 64 x 68 (padded)
    float* sw2 = sw1 + 64 * 68;      // 64 x 64
    float* sw3 = sw2 + 64 * 64;      // 128 x 64
    float* sb1 = sw3 + 128 * 64;     // 64
    float* sb2 = sb1 + 64;           // 64
    float* sb3 = sb2 + 64;           // 128

    const int tid = threadIdx.x;
    for (int i = tid; i < 64 * CIN; i += 128) sw1[(i / CIN) * 68 + (i % CIN)] = w1[i];
    for (int i = tid; i < 64 * 64; i += 128) sw2[i] = w2[i];
    for (int i = tid; i < 128 * 64; i += 128) sw3[i] = w3[i];
    if (tid < 64) {
        sb1[tid] = b1[tid];
        sb2[tid] = b2[tid];
    }
    if (tid < 128) sb3[tid] = b3[tid];
    __syncthreads();

    const int warp = tid >> 5, lane = tid & 31;
    const int pc = blockIdx.x * 4 + warp;  // global centroid id
    const int b = pc >> 10, p = pc & 1023;

    const int idx = g_nidx[pc * NS + lane];
    const float* P = xyz + ((size_t)b * NN + idx) * 3;
    const float* NXp = newxyz + (size_t)pc * 3;

    float in[CIN];
    in[0] = P[0] - NXp[0];
    in[1] = P[1] - NXp[1];
    in[2] = P[2] - NXp[2];
    const float4* F = (const float4*)(feat + ((size_t)b * NN + idx) * CF);
#pragma unroll
    for (int q = 0; q < 16; q++) {
        const float4 v = F[q];
        in[3 + 4 * q] = v.x;
        in[4 + 4 * q] = v.y;
        in[5 + 4 * q] = v.z;
        in[6 + 4 * q] = v.w;
    }

    float h1[64] __attribute__((aligned(16)));
#pragma unroll 1
    for (int o = 0; o < 64; o += 8) {
        float acc[8];
#pragma unroll
        for (int j = 0; j < 8; j++) acc[j] = sb1[o + j];
#pragma unroll
        for (int c = 0; c < 64; c += 4) {
#pragma unroll
            for (int j = 0; j < 8; j++) {
                const float4 w = *(const float4*)&sw1[(o + j) * 68 + c];
                acc[j] = fmaf(in[c + 0], w.x, acc[j]);
                acc[j] = fmaf(in[c + 1], w.y, acc[j]);
                acc[j] = fmaf(in[c + 2], w.z, acc[j]);
                acc[j] = fmaf(in[c + 3], w.w, acc[j]);
            }
        }
#pragma unroll
        for (int j = 0; j < 8; j++) {
            acc[j] = fmaf(in[64], sw1[(o + j) * 68 + 64], acc[j]);
            acc[j] = fmaf(in[65], sw1[(o + j) * 68 + 65], acc[j]);
            acc[j] = fmaf(in[66], sw1[(o + j) * 68 + 66], acc[j]);
            h1[o + j] = fmaxf(acc[j], 0.0f);
        }
    }

    float h2[64] __attribute__((aligned(16)));
#pragma unroll 1
    for (int o = 0; o < 64; o += 8) {
        float acc[8];
#pragma unroll
        for (int j = 0; j < 8; j++) acc[j] = sb2[o + j];
#pragma unroll
        for (int c = 0; c < 64; c += 4) {
            const float4 hv = *(const float4*)&h1[c];
#pragma unroll
            for (int j = 0; j < 8; j++) {
                const float4 w = *(const float4*)&sw2[(o + j) * 64 + c];
                acc[j] = fmaf(hv.x, w.x, acc[j]);
                acc[j] = fmaf(hv.y, w.y, acc[j]);
                acc[j] = fmaf(hv.z, w.z, acc[j]);
                acc[j] = fmaf(hv.w, w.w, acc[j]);
            }
        }
#pragma unroll
        for (int j = 0; j < 8; j++) h2[o + j] = fmaxf(acc[j], 0.0f);
    }

    const size_t obase = ((size_t)b * 128) * NPT + p;
#pragma unroll 1
    for (int o = 0; o < 128; o += 8) {
        float acc[8];
#pragma unroll
        for (int j = 0; j < 8; j++) acc[j] = sb3[o + j];
#pragma unroll
        for (int c = 0; c < 64; c += 4) {
            const float4 hv = *(const float4*)&h2[c];
#pragma unroll
            for (int j = 0; j < 8; j++) {
                const float4 w = *(const float4*)&sw3[(o + j) * 64 + c];
                acc[j] = fmaf(hv.x, w.x, acc[j]);
                acc[j] = fmaf(hv.y, w.y, acc[j]);
                acc[j] = fmaf(hv.z, w.z, acc[j]);
                acc[j] = fmaf(hv.w, w.w, acc[j]);
            }
        }
#pragma unroll
        for (int j = 0; j < 8; j++) {
            float v = fmaxf(acc[j], 0.0f);  // relu then max over samples
#pragma unroll
            for (int off = 16; off; off >>= 1)
                v = fmaxf(v, __shfl_xor_sync(0xffffffffu, v, off));
            if (lane == 0) outf[obase + (size_t)(o + j) * NPT] = v;
        }
    }
}

// ---------------------------------------------------------------------------
extern "C" void kernel_launch(void* const* d_in, const int* in_sizes, int n_in,
                              void* d_out, int out_size) {
    const float* xyz = (const float*)d_in[0];
    const float* feat = (const float*)d_in[1];
    const float* w1 = (const float*)d_in[2];
    const float* b1 = (const float*)d_in[3];
    const float* w2 = (const float*)d_in[4];
    const float* b2 = (const float*)d_in[5];
    const float* w3 = (const float*)d_in[6];
    const float* b3 = (const float*)d_in[7];

    float* out = (float*)d_out;
    float* newxyz = out;                  // (B, NPOINT, 3)
    float* outf = out + BB * NPT * 3;     // (B, 128, NPOINT)

    const int fps_smem = 8192 * 16 + 8192 * 8;  // 196608 B (full packed copy)
    const int mlp_smem = (64 * 68 + 64 * 64 + 128 * 64 + 64 + 64 + 128) * 4;  // 67584 B

    cudaFuncSetAttribute(fps_kernel, cudaFuncAttributeMaxDynamicSharedMemorySize, fps_smem);
    cudaFuncSetAttribute(mlp_kernel, cudaFuncAttributeMaxDynamicSharedMemorySize, mlp_smem);

    fps_kernel<<<BB * CL, 1024, fps_smem>>>(xyz, newxyz);
    ball_kernel<<<(BB * NPT * 32) / 256, 256>>>(xyz, newxyz);
    mlp_kernel<<<BB * NPT / 4, 128, mlp_smem>>>(xyz, feat, w1, b1, w2, b2, w3, b3, newxyz, outf);
}